// round 8
// baseline (speedup 1.0000x reference)
#include <cuda_runtime.h>
#include <math.h>

#define BETA 1000000.0f
#define FULL 0xFFFFFFFFu

// compare-exchange: a <- max, b <- min  (descending order)
__device__ __forceinline__ void ce(float& a, float& b) {
    float lo = fminf(a, b);
    a = fmaxf(a, b);
    b = lo;
}

// Batcher odd-even mergesort, 8 inputs, 19 comparators, descending.
__device__ __forceinline__ void sort8_desc(float s[8]) {
    ce(s[0],s[1]); ce(s[2],s[3]); ce(s[4],s[5]); ce(s[6],s[7]);
    ce(s[0],s[2]); ce(s[1],s[3]); ce(s[4],s[6]); ce(s[5],s[7]);
    ce(s[1],s[2]); ce(s[5],s[6]);
    ce(s[0],s[4]); ce(s[1],s[5]); ce(s[2],s[6]); ce(s[3],s[7]);
    ce(s[2],s[4]); ce(s[3],s[5]);
    ce(s[1],s[2]); ce(s[3],s[4]); ce(s[5],s[6]);
}

// a, b sorted descending. a <- top-8 of (a U b), sorted descending.
__device__ __forceinline__ void merge_top8(float a[8], const float b[8]) {
    float m[8];
    #pragma unroll
    for (int i = 0; i < 8; i++) m[i] = fmaxf(a[i], b[7 - i]);
    ce(m[0],m[4]); ce(m[1],m[5]); ce(m[2],m[6]); ce(m[3],m[7]);
    ce(m[0],m[2]); ce(m[1],m[3]); ce(m[4],m[6]); ce(m[5],m[7]);
    ce(m[0],m[1]); ce(m[2],m[3]); ce(m[4],m[5]); ce(m[6],m[7]);
    #pragma unroll
    for (int i = 0; i < 8; i++) a[i] = m[i];
}

// Load one group (4 rows, this lane's 32 values) into v[].
__device__ __forceinline__ void load_group(
    float v[32], const float4* __restrict__ x4, int gi, int g, int j)
{
    const float4* in4 = x4 + ((size_t)(4 * gi + g)) * 64;
    #pragma unroll
    for (int t = 0; t < 8; t++) {
        float4 q = __ldcs(&in4[j + 8 * t]);
        v[4*t+0] = q.x; v[4*t+1] = q.y; v[4*t+2] = q.z; v[4*t+3] = q.w;
    }
}

// Full per-group pipeline: top-8 threshold, speculative store, rare tie fixup.
__device__ __forceinline__ void process_group(
    float v[32], float4* __restrict__ o4, int gi, int g, int j, int lane)
{
    float4* out4 = o4 + ((size_t)(4 * gi + g)) * 64;

    // ---- local top-8 of 32 (sorted descending in s) ----
    float s[8], u[8];
    #pragma unroll
    for (int i = 0; i < 8; i++) s[i] = v[i];
    sort8_desc(s);
    #pragma unroll
    for (int i = 0; i < 8; i++) u[i] = v[8 + i];
    sort8_desc(u);
    merge_top8(s, u);
    #pragma unroll
    for (int i = 0; i < 8; i++) u[i] = v[16 + i];
    sort8_desc(u);
    merge_top8(s, u);
    #pragma unroll
    for (int i = 0; i < 8; i++) u[i] = v[24 + i];
    sort8_desc(u);
    merge_top8(s, u);

    // ---- cross-lane merge within the 8-lane group ----
    #pragma unroll
    for (int d = 1; d < 4; d <<= 1) {
        float p[8];
        #pragma unroll
        for (int i = 0; i < 8; i++) p[i] = __shfl_xor_sync(FULL, s[i], d);
        merge_top8(s, p);
    }
    float t8;
    {
        float p[8];
        #pragma unroll
        for (int i = 0; i < 8; i++) p[i] = __shfl_xor_sync(FULL, s[i], 4);
        float m0 = fmaxf(s[0], p[7]), m1 = fmaxf(s[1], p[6]);
        float m2 = fmaxf(s[2], p[5]), m3 = fmaxf(s[3], p[4]);
        float m4 = fmaxf(s[4], p[3]), m5 = fmaxf(s[5], p[2]);
        float m6 = fmaxf(s[6], p[1]), m7 = fmaxf(s[7], p[0]);
        t8 = fminf(fminf(fminf(m0, m1), fminf(m2, m3)),
                   fminf(fminf(m4, m5), fminf(m6, m7)));
    }

    // ---- speculative fast-path store ----
    #pragma unroll
    for (int t = 0; t < 8; t++) {
        float4 o;
        o.x = (v[4*t+0] >= t8) ? v[4*t+0] : BETA;
        o.y = (v[4*t+1] >= t8) ? v[4*t+1] : BETA;
        o.z = (v[4*t+2] >= t8) ? v[4*t+2] : BETA;
        o.w = (v[4*t+3] >= t8) ? v[4*t+3] : BETA;
        __stcs(&out4[j + 8 * t], o);
    }

    // count of values >= t8 across the group (FADD on fma pipe)
    float nf = 0.0f;
    #pragma unroll
    for (int i = 0; i < 32; i++) nf += (v[i] >= t8) ? 1.0f : 0.0f;
    #pragma unroll
    for (int d = 1; d < 8; d <<= 1) nf += __shfl_xor_sync(FULL, nf, d);

    if (nf != 8.0f) {
        // rare: ties straddle the top-8 boundary -> rewrite row with
        // jax.lax.top_k's lowest-global-index tie-break. Same thread, same
        // addresses: program order makes this the final value.
        unsigned gmask = 0xFFu << (lane & 24);
        unsigned gt = 0, eq = 0;
        #pragma unroll
        for (int i = 0; i < 32; i++) {
            gt |= (v[i] >  t8 ? 1u : 0u) << i;
            eq |= (v[i] == t8 ? 1u : 0u) << i;
        }
        int ngt = __popc(gt);
        #pragma unroll
        for (int d = 1; d < 8; d <<= 1) ngt += __shfl_xor_sync(gmask, ngt, d);

        unsigned sel = gt;
        for (int k = ngt; k < 8; k++) {
            int b = __ffs(eq) - 1;
            int gidx = (eq != 0u) ? ((b >> 2) * 32 + 4 * j + (b & 3)) : 0x7FFFFFFF;
            int gmin = gidx;
            #pragma unroll
            for (int d = 1; d < 8; d <<= 1)
                gmin = min(gmin, __shfl_xor_sync(gmask, gmin, d));
            if (eq != 0u && gidx == gmin) {
                sel |= 1u << b;
                eq &= ~(1u << b);
            }
        }
        #pragma unroll
        for (int t = 0; t < 8; t++) {
            float4 o;
            o.x = ((sel >> (4*t+0)) & 1u) ? v[4*t+0] : BETA;
            o.y = ((sel >> (4*t+1)) & 1u) ? v[4*t+1] : BETA;
            o.z = ((sel >> (4*t+2)) & 1u) ? v[4*t+2] : BETA;
            o.w = ((sel >> (4*t+3)) & 1u) ? v[4*t+3] : BETA;
            __stcs(&out4[j + 8 * t], o);
        }
    }
}

// Persistent warps, double-buffered: next group's 8 loads are always in
// flight while the current group computes -> memory pipe never drains.
__global__ void __launch_bounds__(256, 2) keep_topk_kernel(
    const float* __restrict__ x, float* __restrict__ out, int n_groups)
{
    int lane = threadIdx.x & 31;
    int g = lane >> 3;      // which of the group's 4 rows
    int j = lane & 7;       // lane within the 8-lane row group
    int warp_gid = (blockIdx.x * blockDim.x + threadIdx.x) >> 5;
    int total_warps = (gridDim.x * blockDim.x) >> 5;

    const float4* x4 = reinterpret_cast<const float4*>(x);
    float4* o4 = reinterpret_cast<float4*>(out);

    float vA[32], vB[32];

    int i0 = warp_gid;
    if (i0 >= n_groups) return;
    load_group(vA, x4, i0, g, j);

    while (true) {
        int i1 = i0 + total_warps;
        if (i1 < n_groups) {
            load_group(vB, x4, i1, g, j);          // prefetch while A computes
            process_group(vA, o4, i0, g, j, lane);
            int i2 = i1 + total_warps;
            if (i2 < n_groups) {
                load_group(vA, x4, i2, g, j);      // prefetch while B computes
                process_group(vB, o4, i1, g, j, lane);
                i0 = i2;
            } else {
                process_group(vB, o4, i1, g, j, lane);
                break;
            }
        } else {
            process_group(vA, o4, i0, g, j, lane);
            break;
        }
    }
}

extern "C" void kernel_launch(void* const* d_in, const int* in_sizes, int n_in,
                              void* d_out, int out_size)
{
    const float* x = (const float*)d_in[0];
    float* out = (float*)d_out;
    int n_rows = in_sizes[0] / 256;
    int n_groups = (n_rows + 3) / 4;

    // One resident wave: 2 blocks/SM * 148 SMs (grid-stride handles any SM count)
    int blocks = 296;
    keep_topk_kernel<<<blocks, 256>>>(x, out, n_groups);
}

// round 9
// speedup vs baseline: 1.1186x; 1.1186x over previous
#include <cuda_runtime.h>
#include <math.h>

#define BETA 1000000.0f
#define FULL 0xFFFFFFFFu

// compare-exchange: a <- max, b <- min  (descending order)
__device__ __forceinline__ void ce(float& a, float& b) {
    float lo = fminf(a, b);
    a = fmaxf(a, b);
    b = lo;
}

// 5-comparator descending sort of 4
__device__ __forceinline__ void sort4_desc(float s[4]) {
    ce(s[0],s[1]); ce(s[2],s[3]); ce(s[0],s[2]); ce(s[1],s[3]); ce(s[1],s[2]);
}

// a,b sorted desc. a <- top-4 of (a U b), sorted desc. (4 max + 4 CE)
__device__ __forceinline__ void merge_top4(float a[4], const float b[4]) {
    float m0 = fmaxf(a[0], b[3]);
    float m1 = fmaxf(a[1], b[2]);
    float m2 = fmaxf(a[2], b[1]);
    float m3 = fmaxf(a[3], b[0]);
    ce(m0, m2); ce(m1, m3);
    ce(m0, m1); ce(m2, m3);
    a[0]=m0; a[1]=m1; a[2]=m2; a[3]=m3;
}

// Batcher odd-even mergesort, 8 inputs, 19 comparators, descending.
__device__ __forceinline__ void sort8_desc(float s[8]) {
    ce(s[0],s[1]); ce(s[2],s[3]); ce(s[4],s[5]); ce(s[6],s[7]);
    ce(s[0],s[2]); ce(s[1],s[3]); ce(s[4],s[6]); ce(s[5],s[7]);
    ce(s[1],s[2]); ce(s[5],s[6]);
    ce(s[0],s[4]); ce(s[1],s[5]); ce(s[2],s[6]); ce(s[3],s[7]);
    ce(s[2],s[4]); ce(s[3],s[5]);
    ce(s[1],s[2]); ce(s[3],s[4]); ce(s[5],s[6]);
}

// a, b sorted descending. a <- top-8 of (a U b), sorted descending.
__device__ __forceinline__ void merge_top8(float a[8], const float b[8]) {
    float m[8];
    #pragma unroll
    for (int i = 0; i < 8; i++) m[i] = fmaxf(a[i], b[7 - i]);
    ce(m[0],m[4]); ce(m[1],m[5]); ce(m[2],m[6]); ce(m[3],m[7]);
    ce(m[0],m[2]); ce(m[1],m[3]); ce(m[4],m[6]); ce(m[5],m[7]);
    ce(m[0],m[1]); ce(m[2],m[3]); ce(m[4],m[5]); ce(m[6],m[7]);
    #pragma unroll
    for (int i = 0; i < 8; i++) a[i] = m[i];
}

// 4 rows per warp: 8-lane group per row, 32 values per lane (all registers).
// SPECULATIVE path: per-lane top-4 only (covers the row's top-8 unless one
// lane holds >=5 of them, ~1% of rows). Validity check: count(v>=t8')==8.
// Failure (incl. boundary ties) -> exact fallback.
__global__ void __launch_bounds__(256, 4) keep_topk_kernel(
    const float* __restrict__ x, float* __restrict__ out, int n_rows)
{
    int lane = threadIdx.x & 31;
    int warp = (blockIdx.x * blockDim.x + threadIdx.x) >> 5;
    int g = lane >> 3;     // which of the warp's 4 rows
    int j = lane & 7;      // lane within the 8-lane row group
    int row = warp * 4 + g;
    bool valid = (row < n_rows);
    int row_c = valid ? row : (n_rows - 1);   // keep all lanes shuffle-active

    const float4* in4 = reinterpret_cast<const float4*>(x) + (size_t)row_c * 64;
    float4* out4 = reinterpret_cast<float4*>(out) + (size_t)row_c * 64;

    // lane j holds row elements 32t + 4j + c (t=0..7, c=0..3), slot b = 4t+c
    float v[32];
    #pragma unroll
    for (int t = 0; t < 8; t++) {
        float4 q = __ldcs(&in4[j + 8 * t]);
        v[4*t+0] = q.x; v[4*t+1] = q.y; v[4*t+2] = q.z; v[4*t+3] = q.w;
    }

    // ---- speculative local top-4 of 32 (sorted desc in A) ----
    float A[4], B[4], C[4], D[4];
    #pragma unroll
    for (int i = 0; i < 4; i++) { A[i] = v[i];      B[i] = v[4 + i]; }
    sort4_desc(A); sort4_desc(B); merge_top4(A, B);          // top4(0..7)
    #pragma unroll
    for (int i = 0; i < 4; i++) { B[i] = v[8 + i];  C[i] = v[12 + i]; }
    sort4_desc(B); sort4_desc(C); merge_top4(B, C);          // top4(8..15)
    merge_top4(A, B);                                        // top4(0..15)
    #pragma unroll
    for (int i = 0; i < 4; i++) { B[i] = v[16 + i]; C[i] = v[20 + i]; }
    sort4_desc(B); sort4_desc(C); merge_top4(B, C);          // top4(16..23)
    #pragma unroll
    for (int i = 0; i < 4; i++) { C[i] = v[24 + i]; D[i] = v[28 + i]; }
    sort4_desc(C); sort4_desc(D); merge_top4(C, D);          // top4(24..31)
    merge_top4(B, C);                                        // top4(16..31)
    merge_top4(A, B);                                        // top4(0..31)

    // ---- cross-lane: d=1 bitonic merge of two sorted-4 -> sorted 8 ----
    float s[8];
    {
        float p0 = __shfl_xor_sync(FULL, A[0], 1);
        float p1 = __shfl_xor_sync(FULL, A[1], 1);
        float p2 = __shfl_xor_sync(FULL, A[2], 1);
        float p3 = __shfl_xor_sync(FULL, A[3], 1);
        // bitonic sequence: A desc then partner ascending
        s[0]=A[0]; s[1]=A[1]; s[2]=A[2]; s[3]=A[3];
        s[4]=p3;   s[5]=p2;   s[6]=p1;   s[7]=p0;
        ce(s[0],s[4]); ce(s[1],s[5]); ce(s[2],s[6]); ce(s[3],s[7]);
        ce(s[0],s[2]); ce(s[1],s[3]); ce(s[4],s[6]); ce(s[5],s[7]);
        ce(s[0],s[1]); ce(s[2],s[3]); ce(s[4],s[5]); ce(s[6],s[7]);
    }
    // d=2: full top-8 merge of survivor lists
    {
        float p[8];
        #pragma unroll
        for (int i = 0; i < 8; i++) p[i] = __shfl_xor_sync(FULL, s[i], 2);
        merge_top8(s, p);
    }
    // d=4: relaxed — t8' = min of merged top-8 multiset of survivors
    float t8;
    {
        float p[8];
        #pragma unroll
        for (int i = 0; i < 8; i++) p[i] = __shfl_xor_sync(FULL, s[i], 4);
        float m0 = fmaxf(s[0], p[7]), m1 = fmaxf(s[1], p[6]);
        float m2 = fmaxf(s[2], p[5]), m3 = fmaxf(s[3], p[4]);
        float m4 = fmaxf(s[4], p[3]), m5 = fmaxf(s[5], p[2]);
        float m6 = fmaxf(s[6], p[1]), m7 = fmaxf(s[7], p[0]);
        t8 = fminf(fminf(fminf(m0, m1), fminf(m2, m3)),
                   fminf(fminf(m4, m5), fminf(m6, m7)));
    }

    // ---- speculative store ----
    if (valid) {
        #pragma unroll
        for (int t = 0; t < 8; t++) {
            float4 o;
            o.x = (v[4*t+0] >= t8) ? v[4*t+0] : BETA;
            o.y = (v[4*t+1] >= t8) ? v[4*t+1] : BETA;
            o.z = (v[4*t+2] >= t8) ? v[4*t+2] : BETA;
            o.w = (v[4*t+3] >= t8) ? v[4*t+3] : BETA;
            __stcs(&out4[j + 8 * t], o);
        }
    }

    // validity check: exactly 8 row values >= t8'?  (FADD on fma pipe)
    float nf = 0.0f;
    #pragma unroll
    for (int i = 0; i < 32; i++) nf += (v[i] >= t8) ? 1.0f : 0.0f;
    #pragma unroll
    for (int d = 1; d < 8; d <<= 1) nf += __shfl_xor_sync(FULL, nf, d);

    if (nf != 8.0f) {
        // ---- exact fallback (rare, group-uniform): full top-8 pipeline ----
        unsigned gmask = 0xFFu << (lane & 24);  // this group's lanes
        float u[8];
        #pragma unroll
        for (int i = 0; i < 8; i++) s[i] = v[i];
        sort8_desc(s);
        #pragma unroll
        for (int i = 0; i < 8; i++) u[i] = v[8 + i];
        sort8_desc(u); merge_top8(s, u);
        #pragma unroll
        for (int i = 0; i < 8; i++) u[i] = v[16 + i];
        sort8_desc(u); merge_top8(s, u);
        #pragma unroll
        for (int i = 0; i < 8; i++) u[i] = v[24 + i];
        sort8_desc(u); merge_top8(s, u);

        #pragma unroll
        for (int d = 1; d < 4; d <<= 1) {
            float p[8];
            #pragma unroll
            for (int i = 0; i < 8; i++) p[i] = __shfl_xor_sync(gmask, s[i], d);
            merge_top8(s, p);
        }
        float t8x;
        {
            float p[8];
            #pragma unroll
            for (int i = 0; i < 8; i++) p[i] = __shfl_xor_sync(gmask, s[i], 4);
            float m0 = fmaxf(s[0], p[7]), m1 = fmaxf(s[1], p[6]);
            float m2 = fmaxf(s[2], p[5]), m3 = fmaxf(s[3], p[4]);
            float m4 = fmaxf(s[4], p[3]), m5 = fmaxf(s[5], p[2]);
            float m6 = fmaxf(s[6], p[1]), m7 = fmaxf(s[7], p[0]);
            t8x = fminf(fminf(fminf(m0, m1), fminf(m2, m3)),
                        fminf(fminf(m4, m5), fminf(m6, m7)));
        }

        // exact selection with jax.lax.top_k lowest-index tie-break
        unsigned gt = 0, eq = 0;
        #pragma unroll
        for (int i = 0; i < 32; i++) {
            gt |= (v[i] >  t8x ? 1u : 0u) << i;
            eq |= (v[i] == t8x ? 1u : 0u) << i;
        }
        int ngt = __popc(gt);
        #pragma unroll
        for (int d = 1; d < 8; d <<= 1) ngt += __shfl_xor_sync(gmask, ngt, d);

        unsigned sel = gt;
        for (int k = ngt; k < 8; k++) {
            int b = __ffs(eq) - 1;  // lowest eq slot = lowest global idx in lane
            int gidx = (eq != 0u) ? ((b >> 2) * 32 + 4 * j + (b & 3)) : 0x7FFFFFFF;
            int gmin = gidx;
            #pragma unroll
            for (int d = 1; d < 8; d <<= 1)
                gmin = min(gmin, __shfl_xor_sync(gmask, gmin, d));
            if (eq != 0u && gidx == gmin) {
                sel |= 1u << b;
                eq &= ~(1u << b);
            }
        }
        if (valid) {
            // same thread, same addresses: program order makes this final
            #pragma unroll
            for (int t = 0; t < 8; t++) {
                float4 o;
                o.x = ((sel >> (4*t+0)) & 1u) ? v[4*t+0] : BETA;
                o.y = ((sel >> (4*t+1)) & 1u) ? v[4*t+1] : BETA;
                o.z = ((sel >> (4*t+2)) & 1u) ? v[4*t+2] : BETA;
                o.w = ((sel >> (4*t+3)) & 1u) ? v[4*t+3] : BETA;
                __stcs(&out4[j + 8 * t], o);
            }
        }
    }
}

extern "C" void kernel_launch(void* const* d_in, const int* in_sizes, int n_in,
                              void* d_out, int out_size)
{
    const float* x = (const float*)d_in[0];
    float* out = (float*)d_out;
    int n_rows = in_sizes[0] / 256;

    // 256 threads = 8 warps = 32 rows per block
    int blocks = (n_rows + 31) / 32;
    keep_topk_kernel<<<blocks, 256>>>(x, out, n_rows);
}

// round 10
// speedup vs baseline: 1.1636x; 1.0402x over previous
#include <cuda_runtime.h>
#include <math.h>

#define BETA 1000000.0f
#define FULL 0xFFFFFFFFu

// compare-exchange: a <- max, b <- min  (descending order)
__device__ __forceinline__ void ce(float& a, float& b) {
    float lo = fminf(a, b);
    a = fmaxf(a, b);
    b = lo;
}

// 5-comparator descending sort of 4
__device__ __forceinline__ void sort4_desc(float s[4]) {
    ce(s[0],s[1]); ce(s[2],s[3]); ce(s[0],s[2]); ce(s[1],s[3]); ce(s[1],s[2]);
}

// a,b sorted desc. a <- top-4 of (a U b), sorted desc.
__device__ __forceinline__ void merge_top4(float a[4], const float b[4]) {
    float m0 = fmaxf(a[0], b[3]);
    float m1 = fmaxf(a[1], b[2]);
    float m2 = fmaxf(a[2], b[1]);
    float m3 = fmaxf(a[3], b[0]);
    ce(m0, m2); ce(m1, m3);
    ce(m0, m1); ce(m2, m3);
    a[0]=m0; a[1]=m1; a[2]=m2; a[3]=m3;
}

// top-4 of one 8-block (v[base..base+7]) merged into accumulator A.
// Keeps only two 4-buffers live at a time.
__device__ __forceinline__ void accum_top4_block(float A[4], const float* v) {
    float B[4] = {v[0], v[1], v[2], v[3]};
    float C[4] = {v[4], v[5], v[6], v[7]};
    sort4_desc(B); sort4_desc(C);
    merge_top4(B, C);
    merge_top4(A, B);
}

// Batcher odd-even mergesort, 8 inputs, 19 comparators, descending.
__device__ __forceinline__ void sort8_desc(float s[8]) {
    ce(s[0],s[1]); ce(s[2],s[3]); ce(s[4],s[5]); ce(s[6],s[7]);
    ce(s[0],s[2]); ce(s[1],s[3]); ce(s[4],s[6]); ce(s[5],s[7]);
    ce(s[1],s[2]); ce(s[5],s[6]);
    ce(s[0],s[4]); ce(s[1],s[5]); ce(s[2],s[6]); ce(s[3],s[7]);
    ce(s[2],s[4]); ce(s[3],s[5]);
    ce(s[1],s[2]); ce(s[3],s[4]); ce(s[5],s[6]);
}

// a, b sorted descending. a <- top-8 of (a U b), sorted descending.
__device__ __forceinline__ void merge_top8(float a[8], const float b[8]) {
    float m[8];
    #pragma unroll
    for (int i = 0; i < 8; i++) m[i] = fmaxf(a[i], b[7 - i]);
    ce(m[0],m[4]); ce(m[1],m[5]); ce(m[2],m[6]); ce(m[3],m[7]);
    ce(m[0],m[2]); ce(m[1],m[3]); ce(m[4],m[6]); ce(m[5],m[7]);
    ce(m[0],m[1]); ce(m[2],m[3]); ce(m[4],m[5]); ce(m[6],m[7]);
    #pragma unroll
    for (int i = 0; i < 8; i++) a[i] = m[i];
}

// 4 rows per warp: 8-lane group per row, 32 values per lane (all registers).
// SPECULATIVE: per-lane top-4 covers the row's top-8 unless one lane holds
// >=5 of them (~1% of rows). Validity check: count(v >= t8') == 8.
// 3 blocks/SM -> 85-reg budget so the spec path never spills to local.
__global__ void __launch_bounds__(256, 3) keep_topk_kernel(
    const float* __restrict__ x, float* __restrict__ out, int n_rows)
{
    int lane = threadIdx.x & 31;
    int warp = (blockIdx.x * blockDim.x + threadIdx.x) >> 5;
    int g = lane >> 3;     // which of the warp's 4 rows
    int j = lane & 7;      // lane within the 8-lane row group
    int row = warp * 4 + g;
    bool valid = (row < n_rows);
    int row_c = valid ? row : (n_rows - 1);   // keep all lanes shuffle-active

    const float4* in4 = reinterpret_cast<const float4*>(x) + (size_t)row_c * 64;
    float4* out4 = reinterpret_cast<float4*>(out) + (size_t)row_c * 64;

    // lane j holds row elements 32t + 4j + c (t=0..7, c=0..3), slot b = 4t+c
    float v[32];
    #pragma unroll
    for (int t = 0; t < 8; t++) {
        float4 q = __ldcs(&in4[j + 8 * t]);
        v[4*t+0] = q.x; v[4*t+1] = q.y; v[4*t+2] = q.z; v[4*t+3] = q.w;
    }

    // ---- speculative local top-4 of 32 (sorted desc in A); low live-set ----
    float A[4] = {v[0], v[1], v[2], v[3]};
    sort4_desc(A);
    {
        float B[4] = {v[4], v[5], v[6], v[7]};
        sort4_desc(B);
        merge_top4(A, B);
    }
    accum_top4_block(A, v + 8);
    accum_top4_block(A, v + 16);
    accum_top4_block(A, v + 24);

    // ---- cross-lane: d=1 bitonic merge of two sorted-4 -> sorted 8 ----
    float s[8];
    {
        float p0 = __shfl_xor_sync(FULL, A[0], 1);
        float p1 = __shfl_xor_sync(FULL, A[1], 1);
        float p2 = __shfl_xor_sync(FULL, A[2], 1);
        float p3 = __shfl_xor_sync(FULL, A[3], 1);
        s[0]=A[0]; s[1]=A[1]; s[2]=A[2]; s[3]=A[3];
        s[4]=p3;   s[5]=p2;   s[6]=p1;   s[7]=p0;   // bitonic
        ce(s[0],s[4]); ce(s[1],s[5]); ce(s[2],s[6]); ce(s[3],s[7]);
        ce(s[0],s[2]); ce(s[1],s[3]); ce(s[4],s[6]); ce(s[5],s[7]);
        ce(s[0],s[1]); ce(s[2],s[3]); ce(s[4],s[5]); ce(s[6],s[7]);
    }
    // d=2: full top-8 merge of survivor lists
    {
        float p[8];
        #pragma unroll
        for (int i = 0; i < 8; i++) p[i] = __shfl_xor_sync(FULL, s[i], 2);
        merge_top8(s, p);
    }
    // d=4: relaxed — t8' = min of merged top-8 multiset of survivors
    float t8;
    {
        float p[8];
        #pragma unroll
        for (int i = 0; i < 8; i++) p[i] = __shfl_xor_sync(FULL, s[i], 4);
        float m0 = fmaxf(s[0], p[7]), m1 = fmaxf(s[1], p[6]);
        float m2 = fmaxf(s[2], p[5]), m3 = fmaxf(s[3], p[4]);
        float m4 = fmaxf(s[4], p[3]), m5 = fmaxf(s[5], p[2]);
        float m6 = fmaxf(s[6], p[1]), m7 = fmaxf(s[7], p[0]);
        t8 = fminf(fminf(fminf(m0, m1), fminf(m2, m3)),
                   fminf(fminf(m4, m5), fminf(m6, m7)));
    }

    // ---- speculative store ----
    if (valid) {
        #pragma unroll
        for (int t = 0; t < 8; t++) {
            float4 o;
            o.x = (v[4*t+0] >= t8) ? v[4*t+0] : BETA;
            o.y = (v[4*t+1] >= t8) ? v[4*t+1] : BETA;
            o.z = (v[4*t+2] >= t8) ? v[4*t+2] : BETA;
            o.w = (v[4*t+3] >= t8) ? v[4*t+3] : BETA;
            __stcs(&out4[j + 8 * t], o);
        }
    }

    // validity check: exactly 8 row values >= t8'?  (FADD on fma pipe)
    float nf = 0.0f;
    #pragma unroll
    for (int i = 0; i < 32; i++) nf += (v[i] >= t8) ? 1.0f : 0.0f;
    #pragma unroll
    for (int d = 1; d < 8; d <<= 1) nf += __shfl_xor_sync(FULL, nf, d);

    if (nf != 8.0f) {
        // ---- exact fallback (rare, group-uniform): full top-8 pipeline ----
        unsigned gmask = 0xFFu << (lane & 24);  // this group's lanes
        float u[8];
        #pragma unroll
        for (int i = 0; i < 8; i++) s[i] = v[i];
        sort8_desc(s);
        #pragma unroll
        for (int i = 0; i < 8; i++) u[i] = v[8 + i];
        sort8_desc(u); merge_top8(s, u);
        #pragma unroll
        for (int i = 0; i < 8; i++) u[i] = v[16 + i];
        sort8_desc(u); merge_top8(s, u);
        #pragma unroll
        for (int i = 0; i < 8; i++) u[i] = v[24 + i];
        sort8_desc(u); merge_top8(s, u);

        #pragma unroll
        for (int d = 1; d < 4; d <<= 1) {
            float p[8];
            #pragma unroll
            for (int i = 0; i < 8; i++) p[i] = __shfl_xor_sync(gmask, s[i], d);
            merge_top8(s, p);
        }
        float t8x;
        {
            float p[8];
            #pragma unroll
            for (int i = 0; i < 8; i++) p[i] = __shfl_xor_sync(gmask, s[i], 4);
            float m0 = fmaxf(s[0], p[7]), m1 = fmaxf(s[1], p[6]);
            float m2 = fmaxf(s[2], p[5]), m3 = fmaxf(s[3], p[4]);
            float m4 = fmaxf(s[4], p[3]), m5 = fmaxf(s[5], p[2]);
            float m6 = fmaxf(s[6], p[1]), m7 = fmaxf(s[7], p[0]);
            t8x = fminf(fminf(fminf(m0, m1), fminf(m2, m3)),
                        fminf(fminf(m4, m5), fminf(m6, m7)));
        }

        // exact selection with jax.lax.top_k lowest-index tie-break
        unsigned gt = 0, eq = 0;
        #pragma unroll
        for (int i = 0; i < 32; i++) {
            gt |= (v[i] >  t8x ? 1u : 0u) << i;
            eq |= (v[i] == t8x ? 1u : 0u) << i;
        }
        int ngt = __popc(gt);
        #pragma unroll
        for (int d = 1; d < 8; d <<= 1) ngt += __shfl_xor_sync(gmask, ngt, d);

        unsigned sel = gt;
        for (int k = ngt; k < 8; k++) {
            int b = __ffs(eq) - 1;  // lowest eq slot = lowest global idx in lane
            int gidx = (eq != 0u) ? ((b >> 2) * 32 + 4 * j + (b & 3)) : 0x7FFFFFFF;
            int gmin = gidx;
            #pragma unroll
            for (int d = 1; d < 8; d <<= 1)
                gmin = min(gmin, __shfl_xor_sync(gmask, gmin, d));
            if (eq != 0u && gidx == gmin) {
                sel |= 1u << b;
                eq &= ~(1u << b);
            }
        }
        if (valid) {
            // same thread, same addresses: program order makes this final
            #pragma unroll
            for (int t = 0; t < 8; t++) {
                float4 o;
                o.x = ((sel >> (4*t+0)) & 1u) ? v[4*t+0] : BETA;
                o.y = ((sel >> (4*t+1)) & 1u) ? v[4*t+1] : BETA;
                o.z = ((sel >> (4*t+2)) & 1u) ? v[4*t+2] : BETA;
                o.w = ((sel >> (4*t+3)) & 1u) ? v[4*t+3] : BETA;
                __stcs(&out4[j + 8 * t], o);
            }
        }
    }
}

extern "C" void kernel_launch(void* const* d_in, const int* in_sizes, int n_in,
                              void* d_out, int out_size)
{
    const float* x = (const float*)d_in[0];
    float* out = (float*)d_out;
    int n_rows = in_sizes[0] / 256;

    // 256 threads = 8 warps = 32 rows per block
    int blocks = (n_rows + 31) / 32;
    keep_topk_kernel<<<blocks, 256>>>(x, out, n_rows);
}